// round 1
// baseline (speedup 1.0000x reference)
#include <cuda_runtime.h>
#include <cuda_bf16.h>
#include <cstdint>
#include <cstddef>

// Problem constants
#define BB   8
#define TT   16
#define NN   196
#define CC   768
#define HH   12
#define HD   64
#define MROWS (BB*TT*NN)      // 25088
#define C3   (3*CC)           // 2304

// Scratch: device globals (no allocation allowed)
__device__ float g_qkv[(size_t)MROWS * C3];    // [M, 3C]
__device__ float g_xavg[(size_t)MROWS * CC];   // [M, C] — x1 then (x1+x2)*0.5

// ---------------------------------------------------------------------------
// Tiled fp32 GEMM: C[M,N] = A[M,K] * B[K,N] (+ bias). 64x64 tile, BK=16,
// 256 threads, 4x4 micro-tile. All dims exactly divisible (no guards).
// ---------------------------------------------------------------------------
template<bool BIAS>
__global__ void sgemm64(const float* __restrict__ A,
                        const float* __restrict__ Bm,
                        const float* __restrict__ bias,
                        float* __restrict__ Cm,
                        int Kdim, int ldb)
{
    __shared__ float As[16][68];   // transposed A tile, padded (68*4B = 272B rows keep 16B align)
    __shared__ float Bs[16][64];

    const int tid = threadIdx.x;
    const int m0 = blockIdx.y * 64;
    const int n0 = blockIdx.x * 64;

    const int arow = tid >> 2;            // 0..63
    const int ac4  = (tid & 3) * 4;       // 0,4,8,12
    const int brow = tid >> 4;            // 0..15
    const int bc4  = (tid & 15) * 4;      // 0..60

    const int ty = tid >> 4;              // 0..15 -> rows ty*4..+3
    const int tx = tid & 15;              // 0..15 -> cols tx*4..+3

    const float* Aptr = A + (size_t)(m0 + arow) * Kdim + ac4;
    const float* Bptr = Bm + (size_t)brow * ldb + n0 + bc4;

    float acc[4][4];
#pragma unroll
    for (int i = 0; i < 4; i++)
#pragma unroll
        for (int j = 0; j < 4; j++) acc[i][j] = 0.f;

    for (int k0 = 0; k0 < Kdim; k0 += 16) {
        float4 av = *(const float4*)Aptr;
        float4 bv = *(const float4*)Bptr;
        __syncthreads();
        As[ac4 + 0][arow] = av.x;
        As[ac4 + 1][arow] = av.y;
        As[ac4 + 2][arow] = av.z;
        As[ac4 + 3][arow] = av.w;
        *(float4*)&Bs[brow][bc4] = bv;
        __syncthreads();

#pragma unroll
        for (int kk = 0; kk < 16; kk++) {
            float4 a = *(const float4*)&As[kk][ty * 4];
            float4 b = *(const float4*)&Bs[kk][tx * 4];
            acc[0][0] += a.x * b.x; acc[0][1] += a.x * b.y; acc[0][2] += a.x * b.z; acc[0][3] += a.x * b.w;
            acc[1][0] += a.y * b.x; acc[1][1] += a.y * b.y; acc[1][2] += a.y * b.z; acc[1][3] += a.y * b.w;
            acc[2][0] += a.z * b.x; acc[2][1] += a.z * b.y; acc[2][2] += a.z * b.z; acc[2][3] += a.z * b.w;
            acc[3][0] += a.w * b.x; acc[3][1] += a.w * b.y; acc[3][2] += a.w * b.z; acc[3][3] += a.w * b.w;
        }
        Aptr += 16;
        Bptr += (size_t)16 * ldb;
    }

#pragma unroll
    for (int i = 0; i < 4; i++) {
        size_t row = (size_t)(m0 + ty * 4 + i) * ldb;
#pragma unroll
        for (int j = 0; j < 4; j++) {
            int col = n0 + tx * 4 + j;
            float v = acc[i][j];
            if (BIAS) v += bias[col];
            Cm[row + col] = v;
        }
    }
}

// ---------------------------------------------------------------------------
// Spatial attention: one CTA per (b,t,h). K,V resident in smem (stride 65).
// One warp per query row; lanes parallel over keys, then over head-dim.
// Writes x1 into g_xavg.
// ---------------------------------------------------------------------------
__global__ void spatial_attn(const float* __restrict__ qkv, float* __restrict__ xavg)
{
    extern __shared__ float sm[];
    float* Ks = sm;                       // 196*65
    float* Vs = Ks + 196 * 65;            // 196*65
    float* sQ = Vs + 196 * 65;            // 8*64
    float* sP = sQ + 8 * 64;              // 8*196

    const int bid = blockIdx.x;           // bt*H + h
    const int h   = bid % HH;
    const int bt  = bid / HH;
    const float* base = qkv + (size_t)bt * NN * C3 + h * HD;

    // cooperative load of K and V tiles
    for (int idx = threadIdx.x; idx < NN * HD; idx += 256) {
        int m = idx >> 6, d = idx & 63;
        size_t g = (size_t)m * C3 + d;
        Ks[m * 65 + d] = base[g + CC];
        Vs[m * 65 + d] = base[g + 2 * CC];
    }
    __syncthreads();

    const int w = threadIdx.x >> 5;
    const int lane = threadIdx.x & 31;
    float* myQ = sQ + w * HD;
    float* myP = sP + w * NN;

    for (int r = w; r < NN; r += 8) {
        // load q row into smem (warp-private slot)
        const float* qrow = base + (size_t)r * C3;
        myQ[lane]      = qrow[lane];
        myQ[lane + 32] = qrow[lane + 32];
        __syncwarp();

        // scores: lane handles keys m = lane + 32j
        float sc[7];
#pragma unroll
        for (int j = 0; j < 7; j++) sc[j] = 0.f;
#pragma unroll 8
        for (int d = 0; d < HD; d++) {
            float qd = myQ[d];
#pragma unroll
            for (int j = 0; j < 7; j++) {
                int m = lane + 32 * j;        // may exceed 195; stays inside smem, masked below
                sc[j] += qd * Ks[m * 65 + d];
            }
        }
        float mx = -1e30f;
#pragma unroll
        for (int j = 0; j < 7; j++) {
            int m = lane + 32 * j;
            sc[j] = (m < NN) ? sc[j] * 0.125f : -1e30f;
            mx = fmaxf(mx, sc[j]);
        }
#pragma unroll
        for (int o = 16; o; o >>= 1) mx = fmaxf(mx, __shfl_xor_sync(0xffffffffu, mx, o));
        float sum = 0.f;
#pragma unroll
        for (int j = 0; j < 7; j++) {
            int m = lane + 32 * j;
            float e = (m < NN) ? expf(sc[j] - mx) : 0.f;
            sc[j] = e;
            sum += e;
        }
#pragma unroll
        for (int o = 16; o; o >>= 1) sum += __shfl_xor_sync(0xffffffffu, sum, o);
        float inv = 1.f / sum;
#pragma unroll
        for (int j = 0; j < 7; j++) {
            int m = lane + 32 * j;
            if (m < NN) myP[m] = sc[j] * inv;
        }
        __syncwarp();

        // out[d] = sum_m p[m] * V[m][d], lanes over d
        float a0 = 0.f, a1 = 0.f;
        for (int m = 0; m < NN; m++) {
            float p = myP[m];
            a0 += p * Vs[m * 65 + lane];
            a1 += p * Vs[m * 65 + 32 + lane];
        }
        size_t o = ((size_t)bt * NN + r) * CC + h * HD;
        xavg[o + lane]      = a0;
        xavg[o + 32 + lane] = a1;
        __syncwarp();
    }
}

// ---------------------------------------------------------------------------
// Temporal attention: 4 warps/CTA, one (b,h,n) instance per warp.
// q/k/v (16x64 each) staged in smem (stride 65). Lane t (<16) owns query row t.
// Output staged back through smem so the (x1+x2)*0.5 RMW is coalesced.
// ---------------------------------------------------------------------------
__global__ void temporal_attn(const float* __restrict__ qkv, float* __restrict__ xavg)
{
    extern __shared__ float sm[];
    const int w = threadIdx.x >> 5;
    const int lane = threadIdx.x & 31;
    float* qs = sm + (size_t)w * 3 * 16 * 65;
    float* ks = qs + 16 * 65;
    float* vs = ks + 16 * 65;

    const int inst = blockIdx.x * 4 + w;     // 0..18815 (exact)
    const int n  = inst % NN;
    const int bh = inst / NN;
    const int h  = bh % HH;
    const int b  = bh / HH;

    const size_t tstride = (size_t)NN * C3;  // stride between frames
    const float* base = qkv + ((size_t)(b * TT) * NN + n) * C3 + h * HD;

    for (int idx = lane; idx < TT * HD; idx += 32) {
        int t = idx >> 6, d = idx & 63;
        size_t g = (size_t)t * tstride + d;
        qs[t * 65 + d] = base[g];
        ks[t * 65 + d] = base[g + CC];
        vs[t * 65 + d] = base[g + 2 * CC];
    }
    __syncwarp();

    float p[TT];
    if (lane < TT) {
        const int t = lane;
        float mx = -1e30f;
#pragma unroll
        for (int s = 0; s < TT; s++) {
            float acc = 0.f;
#pragma unroll 8
            for (int d = 0; d < HD; d++) acc += qs[t * 65 + d] * ks[s * 65 + d];
            acc *= 0.125f;
            p[s] = acc;
            mx = fmaxf(mx, acc);
        }
        float sum = 0.f;
#pragma unroll
        for (int s = 0; s < TT; s++) { p[s] = expf(p[s] - mx); sum += p[s]; }
        float inv = 1.f / sum;
#pragma unroll
        for (int s = 0; s < TT; s++) p[s] *= inv;
    }
    __syncwarp();   // everyone done reading qs (scores computed) before overwrite

    if (lane < TT) {
        const int t = lane;
        for (int d = 0; d < HD; d++) {
            float acc = 0.f;
#pragma unroll
            for (int s = 0; s < TT; s++) acc += p[s] * vs[s * 65 + d];
            qs[t * 65 + d] = acc;                // reuse q slot as output staging
        }
    }
    __syncwarp();

    // coalesced read-modify-write of the averaged buffer
    const size_t obase = ((size_t)(b * TT) * NN + n) * CC + h * HD;
    const size_t ostride = (size_t)NN * CC;
    for (int t = 0; t < TT; t++) {
        size_t o = obase + (size_t)t * ostride;
        float x2a = qs[t * 65 + lane];
        float x2b = qs[t * 65 + 32 + lane];
        xavg[o + lane]      = (xavg[o + lane]      + x2a) * 0.5f;
        xavg[o + 32 + lane] = (xavg[o + 32 + lane] + x2b) * 0.5f;
    }
}

// ---------------------------------------------------------------------------
extern "C" void kernel_launch(void* const* d_in, const int* in_sizes, int n_in,
                              void* d_out, int out_size)
{
    const float* x      = (const float*)d_in[0];
    const float* W_qkv  = (const float*)d_in[1];
    const float* W_proj = (const float*)d_in[2];
    const float* b_proj = (const float*)d_in[3];
    float* out = (float*)d_out;

    float* qkv;  cudaGetSymbolAddress((void**)&qkv,  g_qkv);
    float* xavg; cudaGetSymbolAddress((void**)&xavg, g_xavg);

    const int spat_smem = (196 * 65 * 2 + 8 * 64 + 8 * 196) * 4;   // 110240 B
    const int temp_smem = 4 * 3 * 16 * 65 * 4;                     // 49920 B
    static bool attr_done = false;
    if (!attr_done) {
        cudaFuncSetAttribute(spatial_attn, cudaFuncAttributeMaxDynamicSharedMemorySize, spat_smem);
        cudaFuncSetAttribute(temporal_attn, cudaFuncAttributeMaxDynamicSharedMemorySize, temp_smem);
        attr_done = true;
    }

    // 1) qkv = x @ W_qkv           [25088 x 768] * [768 x 2304]
    sgemm64<false><<<dim3(C3 / 64, MROWS / 64), 256>>>(x, W_qkv, nullptr, qkv, CC, C3);
    // 2) spatial attention -> g_xavg (x1)
    spatial_attn<<<BB * TT * HH, 256, spat_smem>>>(qkv, xavg);
    // 3) temporal attention -> g_xavg = (x1 + x2) * 0.5
    temporal_attn<<<(BB * HH * NN) / 4, 128, temp_smem>>>(qkv, xavg);
    // 4) out = g_xavg @ W_proj + b_proj   [25088 x 768] * [768 x 768]
    sgemm64<true><<<dim3(CC / 64, MROWS / 64), 256>>>(xavg, W_proj, b_proj, out, CC, CC);
}

// round 4
// speedup vs baseline: 1.7895x; 1.7895x over previous
#include <cuda_runtime.h>
#include <cuda_bf16.h>
#include <cstdint>
#include <cstddef>

// Problem constants
#define BB   8
#define TT   16
#define NN   196
#define CC   768
#define HH   12
#define HD   64
#define MROWS (BB*TT*NN)      // 25088
#define C3   (3*CC)           // 2304 (qkv width)
#define K3   (3*CC)           // 2304 (tripled-K for bf16 split emulation)

// ---------------------------------------------------------------------------
// Scratch: device globals (no allocation allowed)
// ---------------------------------------------------------------------------
__device__ float g_qkv[(size_t)MROWS * C3];            // [M, 3C] fp32
__device__ float g_xavg[(size_t)MROWS * CC];           // [M, C]  fp32
__device__ __nv_bfloat16 g_x3[(size_t)MROWS * K3];     // [M, 3K] = [hi|hi|lo]
__device__ __nv_bfloat16 g_xavg3[(size_t)MROWS * K3];  // [M, 3K]
__device__ __nv_bfloat16 g_wqkv3[(size_t)C3 * K3];     // [N, 3K] = [hi|lo|hi] (W^T)
__device__ __nv_bfloat16 g_wproj3[(size_t)CC * K3];    // [N, 3K]

// ---------------------------------------------------------------------------
// Helpers
// ---------------------------------------------------------------------------
__device__ __forceinline__ uint32_t smem_u32(const void* p) {
    uint32_t a;
    asm("{ .reg .u64 t; cvta.to.shared.u64 t, %1; cvt.u32.u64 %0, t; }" : "=r"(a) : "l"(p));
    return a;
}
#define SWZ(o) ((o) ^ (((o) >> 3) & 0x70))

__device__ __forceinline__ void cp16(uint32_t d, const void* g) {
    asm volatile("cp.async.cg.shared.global [%0], [%1], 16;" :: "r"(d), "l"(g));
}
__device__ __forceinline__ void ldm_x4(uint32_t* r, uint32_t a) {
    asm volatile("ldmatrix.sync.aligned.m8n8.x4.shared.b16 {%0,%1,%2,%3}, [%4];"
                 : "=r"(r[0]), "=r"(r[1]), "=r"(r[2]), "=r"(r[3]) : "r"(a));
}
__device__ __forceinline__ void mma16816(float* c, const uint32_t* a, const uint32_t* b) {
    asm volatile(
        "mma.sync.aligned.m16n8k16.row.col.f32.bf16.bf16.f32 "
        "{%0,%1,%2,%3}, {%4,%5,%6,%7}, {%8,%9}, {%0,%1,%2,%3};"
        : "+f"(c[0]), "+f"(c[1]), "+f"(c[2]), "+f"(c[3])
        : "r"(a[0]), "r"(a[1]), "r"(a[2]), "r"(a[3]), "r"(b[0]), "r"(b[1]));
}

// ---------------------------------------------------------------------------
// Split fp32 [M,K] row -> bf16 [M,3K] segments [hi | hi | lo].
// ---------------------------------------------------------------------------
__global__ void split3(const float* __restrict__ in, __nv_bfloat16* __restrict__ out, int K)
{
    const int i = blockIdx.x * 256 + threadIdx.x;   // over M*K/4
    const int K4 = K >> 2;
    const int row = i / K4, c = i % K4;
    float4 v = ((const float4*)in)[i];
    __nv_bfloat16 h0 = __float2bfloat16(v.x), h1 = __float2bfloat16(v.y);
    __nv_bfloat16 h2 = __float2bfloat16(v.z), h3 = __float2bfloat16(v.w);
    __nv_bfloat16 l0 = __float2bfloat16(v.x - __bfloat162float(h0));
    __nv_bfloat16 l1 = __float2bfloat16(v.y - __bfloat162float(h1));
    __nv_bfloat16 l2 = __float2bfloat16(v.z - __bfloat162float(h2));
    __nv_bfloat16 l3 = __float2bfloat16(v.w - __bfloat162float(h3));
    __nv_bfloat162 H01; H01.x = h0; H01.y = h1;
    __nv_bfloat162 H23; H23.x = h2; H23.y = h3;
    __nv_bfloat162 L01; L01.x = l0; L01.y = l1;
    __nv_bfloat162 L23; L23.x = l2; L23.y = l3;
    size_t b = (size_t)row * 3 * K;
    __nv_bfloat162* o0 = (__nv_bfloat162*)(out + b) + c * 2;
    __nv_bfloat162* o1 = (__nv_bfloat162*)(out + b + K) + c * 2;
    __nv_bfloat162* o2 = (__nv_bfloat162*)(out + b + 2 * K) + c * 2;
    o0[0] = H01; o0[1] = H23;
    o1[0] = H01; o1[1] = H23;
    o2[0] = L01; o2[1] = L23;
}

// ---------------------------------------------------------------------------
// Transpose+split W [K,N] fp32 -> out [N,3K] bf16, segments [hi | lo | hi].
// ---------------------------------------------------------------------------
__global__ void tsplit(const float* __restrict__ W, __nv_bfloat16* __restrict__ out,
                       int K, int N)
{
    const int i = blockIdx.x * 256 + threadIdx.x;
    const int k = i % K, n = i / K;
    float v = W[(size_t)k * N + n];
    __nv_bfloat16 h = __float2bfloat16(v);
    __nv_bfloat16 l = __float2bfloat16(v - __bfloat162float(h));
    size_t b = (size_t)n * 3 * K;
    out[b + k] = h;
    out[b + K + k] = l;
    out[b + 2 * K + k] = h;
}

// ---------------------------------------------------------------------------
// mma.sync bf16 GEMM: C[M,Ntot] = A[M,Kdim] * B[Ntot,Kdim]^T (+bias).
// CTA tile 128x128, BK=64, 8 warps (warp tile 64x32), cp.async double buffer,
// SW128 swizzle, ldmatrix (non-trans both: A [M,K] and B [N,K] are K-major).
// grid = (Ntot/128, M/128), 256 threads.
// ---------------------------------------------------------------------------
template<bool BIAS>
__global__ void __launch_bounds__(256) gemm_mma(
    const __nv_bfloat16* __restrict__ A,
    const __nv_bfloat16* __restrict__ Bm,
    const float* __restrict__ bias,
    float* __restrict__ Cm,
    int Kdim, int Ntot)
{
    extern __shared__ char smem[];
    const uint32_t sb = smem_u32(smem);
    const int tid = threadIdx.x, wid = tid >> 5, lane = tid & 31;
    const int m0 = blockIdx.y * 128, n0 = blockIdx.x * 128;
    const int wm = (wid >> 2) * 64;        // 0 / 64
    const int wn = (wid & 3) * 32;         // 0,32,64,96

    const __nv_bfloat16* Ag = A + (size_t)m0 * Kdim;
    const __nv_bfloat16* Bg = Bm + (size_t)n0 * Kdim;

    // tile buffers: [buf][A 16KB | B 16KB]
    auto load_tile = [&](int k0, int buf) {
        uint32_t sa = sb + buf * 32768;
        uint32_t sB = sa + 16384;
#pragma unroll
        for (int i = 0; i < 4; i++) {
            int idx = tid + i * 256;          // 0..1023
            int row = idx >> 3, c = idx & 7;  // 128 rows x 8 chunks(16B)
            size_t goff = (size_t)row * Kdim + k0 + c * 8;
            uint32_t soff = SWZ(row * 128 + c * 16);
            cp16(sa + soff, Ag + goff);
            cp16(sB + soff, Bg + goff);
        }
        asm volatile("cp.async.commit_group;" ::: "memory");
    };

    float acc[4][4][4];
#pragma unroll
    for (int i = 0; i < 4; i++)
#pragma unroll
        for (int j = 0; j < 4; j++)
#pragma unroll
            for (int k = 0; k < 4; k++) acc[i][j][k] = 0.f;

    const int nk = Kdim >> 6;              // K / 64
    load_tile(0, 0);

    for (int it = 0; it < nk; ++it) {
        if (it + 1 < nk) {
            load_tile((it + 1) << 6, (it + 1) & 1);
            asm volatile("cp.async.wait_group 1;" ::: "memory");
        } else {
            asm volatile("cp.async.wait_group 0;" ::: "memory");
        }
        __syncthreads();

        uint32_t sa = sb + (it & 1) * 32768;
        uint32_t sB = sa + 16384;
#pragma unroll
        for (int ks = 0; ks < 4; ks++) {
            uint32_t afr[4][4], bfr[2][4];
#pragma unroll
            for (int mt = 0; mt < 4; mt++) {
                int row = wm + mt * 16 + (lane & 15);
                int kb = ks * 32 + ((lane >> 4) << 4);
                ldm_x4(afr[mt], sa + SWZ(row * 128 + kb));
            }
#pragma unroll
            for (int nt2 = 0; nt2 < 2; nt2++) {
                // non-trans: lanes 0-7 -> n0-7/k0-7, 8-15 -> n0-7/k8-15,
                //            16-23 -> n8-15/k0-7, 24-31 -> n8-15/k8-15
                int row = wn + nt2 * 16 + ((lane >> 4) << 3) + (lane & 7);
                int kb = ks * 32 + (((lane >> 3) & 1) << 4);
                ldm_x4(bfr[nt2], sB + SWZ(row * 128 + kb));
            }
#pragma unroll
            for (int mt = 0; mt < 4; mt++)
#pragma unroll
                for (int nt = 0; nt < 4; nt++)
                    mma16816(acc[mt][nt], afr[mt], &bfr[nt >> 1][(nt & 1) * 2]);
        }
        __syncthreads();
    }

    // epilogue: direct float2 stores
#pragma unroll
    for (int mt = 0; mt < 4; mt++) {
        int r0 = m0 + wm + mt * 16 + (lane >> 2);
#pragma unroll
        for (int nt = 0; nt < 4; nt++) {
            int col = n0 + wn + nt * 8 + (lane & 3) * 2;
            float2 v0, v1;
            v0.x = acc[mt][nt][0]; v0.y = acc[mt][nt][1];
            v1.x = acc[mt][nt][2]; v1.y = acc[mt][nt][3];
            if (BIAS) {
                float b0 = bias[col], b1 = bias[col + 1];
                v0.x += b0; v0.y += b1;
                v1.x += b0; v1.y += b1;
            }
            *(float2*)(Cm + (size_t)r0 * Ntot + col) = v0;
            *(float2*)(Cm + (size_t)(r0 + 8) * Ntot + col) = v1;
        }
    }
}

// ---------------------------------------------------------------------------
// Spatial attention: one CTA per (b,t,h). K,V resident in smem (stride 65).
// ---------------------------------------------------------------------------
__global__ void spatial_attn(const float* __restrict__ qkv, float* __restrict__ xavg)
{
    extern __shared__ float sm[];
    float* Ks = sm;                       // 196*65
    float* Vs = Ks + 196 * 65;            // 196*65
    float* sQ = Vs + 196 * 65;            // 8*64
    float* sP = sQ + 8 * 64;              // 8*196

    const int bid = blockIdx.x;
    const int h   = bid % HH;
    const int bt  = bid / HH;
    const float* base = qkv + (size_t)bt * NN * C3 + h * HD;

    for (int idx = threadIdx.x; idx < NN * HD; idx += 256) {
        int m = idx >> 6, d = idx & 63;
        size_t g = (size_t)m * C3 + d;
        Ks[m * 65 + d] = base[g + CC];
        Vs[m * 65 + d] = base[g + 2 * CC];
    }
    __syncthreads();

    const int w = threadIdx.x >> 5;
    const int lane = threadIdx.x & 31;
    float* myQ = sQ + w * HD;
    float* myP = sP + w * NN;

    for (int r = w; r < NN; r += 8) {
        const float* qrow = base + (size_t)r * C3;
        myQ[lane]      = qrow[lane];
        myQ[lane + 32] = qrow[lane + 32];
        __syncwarp();

        float sc[7];
#pragma unroll
        for (int j = 0; j < 7; j++) sc[j] = 0.f;
#pragma unroll 8
        for (int d = 0; d < HD; d++) {
            float qd = myQ[d];
#pragma unroll
            for (int j = 0; j < 7; j++) {
                int m = lane + 32 * j;
                sc[j] += qd * Ks[m * 65 + d];
            }
        }
        float mx = -1e30f;
#pragma unroll
        for (int j = 0; j < 7; j++) {
            int m = lane + 32 * j;
            sc[j] = (m < NN) ? sc[j] * 0.125f : -1e30f;
            mx = fmaxf(mx, sc[j]);
        }
#pragma unroll
        for (int o = 16; o; o >>= 1) mx = fmaxf(mx, __shfl_xor_sync(0xffffffffu, mx, o));
        float sum = 0.f;
#pragma unroll
        for (int j = 0; j < 7; j++) {
            int m = lane + 32 * j;
            float e = (m < NN) ? expf(sc[j] - mx) : 0.f;
            sc[j] = e;
            sum += e;
        }
#pragma unroll
        for (int o = 16; o; o >>= 1) sum += __shfl_xor_sync(0xffffffffu, sum, o);
        float inv = 1.f / sum;
#pragma unroll
        for (int j = 0; j < 7; j++) {
            int m = lane + 32 * j;
            if (m < NN) myP[m] = sc[j] * inv;
        }
        __syncwarp();

        float a0 = 0.f, a1 = 0.f;
        for (int m = 0; m < NN; m++) {
            float p = myP[m];
            a0 += p * Vs[m * 65 + lane];
            a1 += p * Vs[m * 65 + 32 + lane];
        }
        size_t o = ((size_t)bt * NN + r) * CC + h * HD;
        xavg[o + lane]      = a0;
        xavg[o + 32 + lane] = a1;
        __syncwarp();
    }
}

// ---------------------------------------------------------------------------
// Temporal attention: 4 warps/CTA, one (b,h,n) instance per warp.
// ---------------------------------------------------------------------------
__global__ void temporal_attn(const float* __restrict__ qkv, float* __restrict__ xavg)
{
    extern __shared__ float sm[];
    const int w = threadIdx.x >> 5;
    const int lane = threadIdx.x & 31;
    float* qs = sm + (size_t)w * 3 * 16 * 65;
    float* ks = qs + 16 * 65;
    float* vs = ks + 16 * 65;

    const int inst = blockIdx.x * 4 + w;
    const int n  = inst % NN;
    const int bh = inst / NN;
    const int h  = bh % HH;
    const int b  = bh / HH;

    const size_t tstride = (size_t)NN * C3;
    const float* base = qkv + ((size_t)(b * TT) * NN + n) * C3 + h * HD;

    for (int idx = lane; idx < TT * HD; idx += 32) {
        int t = idx >> 6, d = idx & 63;
        size_t g = (size_t)t * tstride + d;
        qs[t * 65 + d] = base[g];
        ks[t * 65 + d] = base[g + CC];
        vs[t * 65 + d] = base[g + 2 * CC];
    }
    __syncwarp();

    float p[TT];
    if (lane < TT) {
        const int t = lane;
        float mx = -1e30f;
#pragma unroll
        for (int s = 0; s < TT; s++) {
            float acc = 0.f;
#pragma unroll 8
            for (int d = 0; d < HD; d++) acc += qs[t * 65 + d] * ks[s * 65 + d];
            acc *= 0.125f;
            p[s] = acc;
            mx = fmaxf(mx, acc);
        }
        float sum = 0.f;
#pragma unroll
        for (int s = 0; s < TT; s++) { p[s] = expf(p[s] - mx); sum += p[s]; }
        float inv = 1.f / sum;
#pragma unroll
        for (int s = 0; s < TT; s++) p[s] *= inv;
    }
    __syncwarp();

    if (lane < TT) {
        const int t = lane;
        for (int d = 0; d < HD; d++) {
            float acc = 0.f;
#pragma unroll
            for (int s = 0; s < TT; s++) acc += p[s] * vs[s * 65 + d];
            qs[t * 65 + d] = acc;
        }
    }
    __syncwarp();

    const size_t obase = ((size_t)(b * TT) * NN + n) * CC + h * HD;
    const size_t ostride = (size_t)NN * CC;
    for (int t = 0; t < TT; t++) {
        size_t o = obase + (size_t)t * ostride;
        float x2a = qs[t * 65 + lane];
        float x2b = qs[t * 65 + 32 + lane];
        xavg[o + lane]      = (xavg[o + lane]      + x2a) * 0.5f;
        xavg[o + 32 + lane] = (xavg[o + 32 + lane] + x2b) * 0.5f;
    }
}

// ---------------------------------------------------------------------------
extern "C" void kernel_launch(void* const* d_in, const int* in_sizes, int n_in,
                              void* d_out, int out_size)
{
    const float* x      = (const float*)d_in[0];
    const float* W_qkv  = (const float*)d_in[1];
    const float* W_proj = (const float*)d_in[2];
    const float* b_proj = (const float*)d_in[3];
    float* out = (float*)d_out;

    float* qkv;   cudaGetSymbolAddress((void**)&qkv,   g_qkv);
    float* xavg;  cudaGetSymbolAddress((void**)&xavg,  g_xavg);
    __nv_bfloat16* x3;     cudaGetSymbolAddress((void**)&x3,     g_x3);
    __nv_bfloat16* xavg3;  cudaGetSymbolAddress((void**)&xavg3,  g_xavg3);
    __nv_bfloat16* wqkv3;  cudaGetSymbolAddress((void**)&wqkv3,  g_wqkv3);
    __nv_bfloat16* wproj3; cudaGetSymbolAddress((void**)&wproj3, g_wproj3);

    const int gemm_smem = 65536;
    const int spat_smem = (196 * 65 * 2 + 8 * 64 + 8 * 196) * 4;   // 110240 B
    const int temp_smem = 4 * 3 * 16 * 65 * 4;                     // 49920 B
    static bool attr_done = false;
    if (!attr_done) {
        cudaFuncSetAttribute(gemm_mma<false>, cudaFuncAttributeMaxDynamicSharedMemorySize, gemm_smem);
        cudaFuncSetAttribute(gemm_mma<true>,  cudaFuncAttributeMaxDynamicSharedMemorySize, gemm_smem);
        cudaFuncSetAttribute(spatial_attn,    cudaFuncAttributeMaxDynamicSharedMemorySize, spat_smem);
        cudaFuncSetAttribute(temporal_attn,   cudaFuncAttributeMaxDynamicSharedMemorySize, temp_smem);
        attr_done = true;
    }

    // 0) operand prep: split x; transpose+split weights
    split3<<<(MROWS * CC / 4) / 256, 256>>>(x, x3, CC);
    tsplit<<<(C3 * CC) / 256, 256>>>(W_qkv, wqkv3, CC, C3);
    tsplit<<<(CC * CC) / 256, 256>>>(W_proj, wproj3, CC, CC);

    // 1) qkv = x @ W_qkv via mma.sync (split-K emulated fp32)
    gemm_mma<false><<<dim3(C3 / 128, MROWS / 128), 256, gemm_smem>>>(
        x3, wqkv3, nullptr, qkv, K3, C3);

    // 2) spatial attention -> g_xavg (x1)
    spatial_attn<<<BB * TT * HH, 256, spat_smem>>>(qkv, xavg);
    // 3) temporal attention -> g_xavg = (x1 + x2) * 0.5
    temporal_attn<<<(BB * HH * NN) / 4, 128, temp_smem>>>(qkv, xavg);

    // 4) split xavg, then out = xavg @ W_proj + b_proj via mma.sync
    split3<<<(MROWS * CC / 4) / 256, 256>>>(xavg, xavg3, CC);
    gemm_mma<true><<<dim3(CC / 128, MROWS / 128), 256, gemm_smem>>>(
        xavg3, wproj3, b_proj, out, K3, CC);
}